// round 13
// baseline (speedup 1.0000x reference)
#include <cuda_runtime.h>
#include <cuda_bf16.h>
#include <math.h>
#include <stdint.h>

// Problem constants
#define NB      4
#define CIN     512
#define HH      64
#define WW      64
#define HW      4096
#define QKVCH   1536
#define NGROUP  192
#define NHEAD   128
#define ATTNCH  1024
#define EPSV    1e-5f
#define BNEPS   1e-5f
#define NCHK    8            // attn pixel chunks

#define KWX  (CIN / 2)
#define KWA  (ATTNCH / 2)

// Scratch
__device__ float g_qkv [(size_t)NB * QKVCH * HW];
__device__ float g_agg [(size_t)NB * QKVCH * HW];
__device__ float g_kvpart[NCHK][NB][NHEAD][72];
__device__ uint32_t g_xh   [(size_t)NB * HW * KWX];
__device__ uint32_t g_xl   [(size_t)NB * HW * KWX];
__device__ uint32_t g_atth [(size_t)NB * HW * KWA];
__device__ uint32_t g_attl [(size_t)NB * HW * KWA];
__device__ uint32_t g_wqh  [QKVCH * KWX];
__device__ uint32_t g_wql  [QKVCH * KWX];
__device__ uint32_t g_wph  [CIN * KWA];
__device__ uint32_t g_wpl  [CIN * KWA];

// ===========================================================================
// Helpers
// ===========================================================================
__device__ __forceinline__ void split_bf16(float x, uint16_t& h, uint16_t& l) {
    __nv_bfloat16 hb = __float2bfloat16_rn(x);
    float r = x - __bfloat162float(hb);
    __nv_bfloat16 lb = __float2bfloat16_rn(r);
    h = __nv_bfloat16_raw(hb).x;
    l = __nv_bfloat16_raw(lb).x;
}
__device__ __forceinline__ uint32_t pack2(uint16_t lo16, uint16_t hi16) {
    return (uint32_t)lo16 | ((uint32_t)hi16 << 16);
}
__device__ __forceinline__ void mma_bf16(float d[4], const uint32_t a[4],
                                         uint32_t b0, uint32_t b1) {
    asm volatile(
        "mma.sync.aligned.m16n8k16.row.col.f32.bf16.bf16.f32 "
        "{%0,%1,%2,%3}, {%4,%5,%6,%7}, {%8,%9}, {%0,%1,%2,%3};\n"
        : "+f"(d[0]), "+f"(d[1]), "+f"(d[2]), "+f"(d[3])
        : "r"(a[0]), "r"(a[1]), "r"(a[2]), "r"(a[3]), "r"(b0), "r"(b1));
}
__device__ __forceinline__ void cpasync16(uint32_t* smem_dst, const uint32_t* gsrc) {
    uint32_t s = (uint32_t)__cvta_generic_to_shared(smem_dst);
    asm volatile("cp.async.ca.shared.global [%0], [%1], 16;" :: "r"(s), "l"(gsrc));
}
#define LDSM_X4(r, addr)                                                      \
    asm volatile("ldmatrix.sync.aligned.m8n8.x4.shared.b16 {%0,%1,%2,%3}, [%4];" \
        : "=r"((r)[0]), "=r"((r)[1]), "=r"((r)[2]), "=r"((r)[3]) : "r"(addr))

// ===========================================================================
// Pre-split kernels
// ===========================================================================
__global__ void presplit_w_kernel(const float* __restrict__ w,
                                  uint32_t* __restrict__ wh,
                                  uint32_t* __restrict__ wl, int nwords) {
    int i = blockIdx.x * blockDim.x + threadIdx.x;
    if (i >= nwords) return;
    float2 v = ((const float2*)w)[i];
    uint16_t h0, l0, h1, l1;
    split_bf16(v.x, h0, l0); split_bf16(v.y, h1, l1);
    wh[i] = pack2(h0, h1);
    wl[i] = pack2(l0, l1);
}
__global__ __launch_bounds__(256)
void presplit_x_kernel(const float* __restrict__ x,
                       uint32_t* __restrict__ xh,
                       uint32_t* __restrict__ xl) {
    __shared__ uint32_t th[64][33];
    __shared__ uint32_t tl[64][33];
    const int t   = threadIdx.x;
    const int b   = blockIdx.z;
    const int cp0 = blockIdx.y * 64;
    const int p0  = blockIdx.x * 32;

#pragma unroll
    for (int it = 0; it < 8; it++) {
        int cp = it * 8 + (t >> 5);
        int p  = t & 31;
        const float* s = x + ((size_t)(b * CIN + 2 * (cp0 + cp))) * HW + p0 + p;
        float a = s[0];
        float c = s[HW];
        uint16_t ha, la, hc, lc;
        split_bf16(a, ha, la); split_bf16(c, hc, lc);
        th[cp][p] = pack2(ha, hc);
        tl[cp][p] = pack2(la, lc);
    }
    __syncthreads();

#pragma unroll
    for (int it = 0; it < 2; it++) {
        int idx = t + it * 256;
        int p   = idx >> 4;
        int c4  = (idx & 15) * 4;
        uint4 hv = make_uint4(th[c4][p], th[c4 + 1][p], th[c4 + 2][p], th[c4 + 3][p]);
        uint4 lv = make_uint4(tl[c4][p], tl[c4 + 1][p], tl[c4 + 2][p], tl[c4 + 3][p]);
        size_t o = ((size_t)b * HW + p0 + p) * KWX + cp0 + c4;
        *(uint4*)(xh + o) = hv;
        *(uint4*)(xl + o) = lv;
    }
}

// ===========================================================================
// tensor GEMM, 2-stage cp.async pipeline (R11 order: prefetch -> wait 1).
// ===========================================================================
#define STRIDE20 20
#define ST_AH 0
#define ST_AL 2560
#define ST_BH 5120
#define ST_BL 7680
#define ST_WORDS 10240
#define SMEM_BYTES (2 * ST_WORDS * 4)

__device__ __forceinline__ void stage_tile(uint32_t* sbase, int t, int KW,
                                           const uint32_t* ahr, const uint32_t* alr,
                                           const uint32_t* bhr, const uint32_t* blr) {
#pragma unroll
    for (int r = 0; r < 2; r++) {
        int id = t + r * 256, o = id >> 2, c4 = (id & 3) * 4;
        cpasync16(sbase + ST_AH + o * STRIDE20 + c4, ahr + (size_t)o * KW + c4);
        cpasync16(sbase + ST_AL + o * STRIDE20 + c4, alr + (size_t)o * KW + c4);
    }
#pragma unroll
    for (int r = 0; r < 2; r++) {
        int id = t + r * 256, n = id >> 2, c4 = (id & 3) * 4;
        cpasync16(sbase + ST_BH + n * STRIDE20 + c4, bhr + (size_t)n * KW + c4);
        cpasync16(sbase + ST_BL + n * STRIDE20 + c4, blr + (size_t)n * KW + c4);
    }
    asm volatile("cp.async.commit_group;" ::: "memory");
}

template <bool BN>
__global__ __launch_bounds__(256, 2)
void mma_gemm_kernel(const uint32_t* __restrict__ Bh_g,
                     const uint32_t* __restrict__ Bl_g,
                     const uint32_t* __restrict__ Ah_g,
                     const uint32_t* __restrict__ Al_g,
                     float* __restrict__ C, int K, int Ochan,
                     const float* __restrict__ bn_gamma,
                     const float* __restrict__ bn_beta,
                     const float* __restrict__ bn_mean,
                     const float* __restrict__ bn_var)
{
    extern __shared__ uint32_t smw[];
    const int KW = K >> 1;
    const int t = threadIdx.x, lane = t & 31, wid = t >> 5;
    const int wm = wid & 3, wn = wid >> 2;
    const int bx = blockIdx.x;
    const int b  = bx >> 5;
    const int p0 = (bx & 31) * 128;
    const int o0 = blockIdx.y * 128;

    const uint32_t* Bhb = Bh_g + ((size_t)b * HW + p0) * KW;
    const uint32_t* Blb = Bl_g + ((size_t)b * HW + p0) * KW;
    const uint32_t* Ahb = Ah_g + (size_t)o0 * KW;
    const uint32_t* Alb = Al_g + (size_t)o0 * KW;

    uint32_t aoff[2];
#pragma unroll
    for (int i = 0; i < 2; i++)
        aoff[i] = ((wm * 32 + i * 16 + (lane & 15)) * STRIDE20 +
                   ((lane >> 4) & 1) * 4) * 4;
    uint32_t boff[4];
#pragma unroll
    for (int jj = 0; jj < 4; jj++)
        boff[jj] = ((wn * 64 + jj * 16 + (lane & 7) + ((lane >> 4) & 1) * 8) * STRIDE20 +
                    ((lane >> 3) & 1) * 4) * 4;

    const uint32_t smem32 = (uint32_t)__cvta_generic_to_shared(smw);

    float acc[2][8][4];
#pragma unroll
    for (int i = 0; i < 2; i++)
#pragma unroll
        for (int j = 0; j < 8; j++)
#pragma unroll
            for (int e = 0; e < 4; e++) acc[i][j][e] = 0.f;

    const int NT = K / 32;
    stage_tile(smw, t, KW, Ahb, Alb, Bhb, Blb);

    for (int kt = 0; kt < NT; kt++) {
        if (kt + 1 < NT) {
            int kw0 = (kt + 1) * 16;
            stage_tile(smw + ((kt + 1) & 1) * ST_WORDS, t, KW,
                       Ahb + kw0, Alb + kw0, Bhb + kw0, Blb + kw0);
            asm volatile("cp.async.wait_group 1;" ::: "memory");
        } else {
            asm volatile("cp.async.wait_group 0;" ::: "memory");
        }
        __syncthreads();

        const uint32_t sb = smem32 + ((kt & 1) ? ST_WORDS * 4 : 0);

#pragma unroll
        for (int s = 0; s < 2; s++) {
            const uint32_t sd = s * 32;
            uint32_t ah[2][4], al[2][4], bb[4][4];
#pragma unroll
            for (int i = 0; i < 2; i++) {
                LDSM_X4(ah[i], sb + ST_AH * 4 + aoff[i] + sd);
                LDSM_X4(al[i], sb + ST_AL * 4 + aoff[i] + sd);
            }
#pragma unroll
            for (int jj = 0; jj < 4; jj++)
                LDSM_X4(bb[jj], sb + ST_BH * 4 + boff[jj] + sd);
#pragma unroll
            for (int jj = 0; jj < 4; jj++)
#pragma unroll
                for (int h = 0; h < 2; h++) {
                    int j = 2 * jj + h;
                    uint32_t b0 = bb[jj][2 * h], b1 = bb[jj][2 * h + 1];
#pragma unroll
                    for (int i = 0; i < 2; i++) {
                        mma_bf16(acc[i][j], ah[i], b0, b1);
                        mma_bf16(acc[i][j], al[i], b0, b1);
                    }
                }
#pragma unroll
            for (int jj = 0; jj < 4; jj++)
                LDSM_X4(bb[jj], sb + ST_BL * 4 + boff[jj] + sd);
#pragma unroll
            for (int jj = 0; jj < 4; jj++)
#pragma unroll
                for (int h = 0; h < 2; h++) {
                    int j = 2 * jj + h;
                    uint32_t b0 = bb[jj][2 * h], b1 = bb[jj][2 * h + 1];
#pragma unroll
                    for (int i = 0; i < 2; i++)
                        mma_bf16(acc[i][j], ah[i], b0, b1);
                }
        }
        __syncthreads();
    }

    const int orow = o0 + wm * 32 + (lane >> 2);
    float scl[4], bia[4];
#pragma unroll
    for (int r = 0; r < 4; r++) {
        if (BN) {
            int o = orow + 8 * r;
            float inv = bn_gamma[o] * rsqrtf(bn_var[o] + BNEPS);
            scl[r] = inv;
            bia[r] = bn_beta[o] - bn_mean[o] * inv;
        } else { scl[r] = 1.f; bia[r] = 0.f; }
    }
    float* Cb = C + (size_t)b * Ochan * HW;
    const int pbase = p0 + wn * 64 + (lane & 3) * 2;
#pragma unroll
    for (int i = 0; i < 2; i++) {
        int oA = orow + 16 * i;
        int r0 = 2 * i;
#pragma unroll
        for (int j = 0; j < 8; j++) {
            int p = pbase + 8 * j;
            float2 v0, v1;
            v0.x = acc[i][j][0] * scl[r0] + bia[r0];
            v0.y = acc[i][j][1] * scl[r0] + bia[r0];
            v1.x = acc[i][j][2] * scl[r0 + 1] + bia[r0 + 1];
            v1.y = acc[i][j][3] * scl[r0 + 1] + bia[r0 + 1];
            *(float2*)&Cb[(size_t)oA * HW + p]       = v0;
            *(float2*)&Cb[(size_t)(oA + 8) * HW + p] = v1;
        }
    }
}

// ---------------------------------------------------------------------------
// Fused depthwise 5x5 + grouped 8x8 pointwise — register sliding window.
// ---------------------------------------------------------------------------
__global__ __launch_bounds__(256)
void dwpw_kernel(const float* __restrict__ w_dw,
                 const float* __restrict__ w_pw)
{
    const int b  = blockIdx.z;
    const int g  = blockIdx.y;
    const int r0 = blockIdx.x * 8;
    const int t  = threadIdx.x;

    __shared__ float sin_[8][12][68];
    __shared__ float sdw[8][8][68];
    __shared__ float swdw[8][25];
    __shared__ float swpw[64];

    const float* src = g_qkv + ((size_t)b * QKVCH + g * 8) * HW;
    float*       dst = g_agg + ((size_t)b * QKVCH + g * 8) * HW;

    if (t < 200) swdw[t / 25][t % 25] = w_dw[(size_t)(g * 8 + t / 25) * 25 + (t % 25)];
    if (t < 64)  swpw[t] = w_pw[(size_t)g * 64 + t];

    for (int idx = t; idx < 8 * 12 * 68; idx += 256) {
        int i   = idx / (12 * 68);
        int rem = idx % (12 * 68);
        int rr  = rem / 68, cc = rem % 68;
        int gr  = r0 + rr - 2, gc = cc - 2;
        float v = 0.f;
        if (gr >= 0 && gr < HH && gc >= 0 && gc < WW)
            v = src[(size_t)i * HW + gr * WW + gc];
        sin_[i][rr][cc] = v;
    }
    __syncthreads();

#pragma unroll
    for (int j = 0; j < 2; j++) {
        int task = t + j * 256;
        int cs = task & 7, rr = (task >> 3) & 7, i = task >> 6;
        float acc0[8];
#pragma unroll
        for (int k = 0; k < 8; k++) acc0[k] = 0.f;
#pragma unroll
        for (int dy = 0; dy < 5; dy++) {
            const float* row = &sin_[i][rr + dy][cs * 8];
            float rbuf[12];
            *(float4*)&rbuf[0] = *(const float4*)&row[0];
            *(float4*)&rbuf[4] = *(const float4*)&row[4];
            *(float4*)&rbuf[8] = *(const float4*)&row[8];
#pragma unroll
            for (int dx = 0; dx < 5; dx++) {
                float wv = swdw[i][dy * 5 + dx];
#pragma unroll
                for (int k = 0; k < 8; k++)
                    acc0[k] = fmaf(rbuf[k + dx], wv, acc0[k]);
            }
        }
        *(float4*)&sdw[i][rr][cs * 8]     = make_float4(acc0[0], acc0[1], acc0[2], acc0[3]);
        *(float4*)&sdw[i][rr][cs * 8 + 4] = make_float4(acc0[4], acc0[5], acc0[6], acc0[7]);
    }
    __syncthreads();

#pragma unroll
    for (int j = 0; j < 2; j++) {
        int task = t + j * 256;
        int cs = task & 7, rr = (task >> 3) & 7, o = task >> 6;
        float acc0[8];
#pragma unroll
        for (int k = 0; k < 8; k++) acc0[k] = 0.f;
#pragma unroll
        for (int i = 0; i < 8; i++) {
            float wv = swpw[o * 8 + i];
            float rbuf[8];
            *(float4*)&rbuf[0] = *(const float4*)&sdw[i][rr][cs * 8];
            *(float4*)&rbuf[4] = *(const float4*)&sdw[i][rr][cs * 8 + 4];
#pragma unroll
            for (int k = 0; k < 8; k++)
                acc0[k] = fmaf(rbuf[k], wv, acc0[k]);
        }
        float* dp = dst + (size_t)o * HW + (r0 + rr) * WW + cs * 8;
        *(float4*)&dp[0] = make_float4(acc0[0], acc0[1], acc0[2], acc0[3]);
        *(float4*)&dp[4] = make_float4(acc0[4], acc0[5], acc0[6], acc0[7]);
    }
}

// ---------------------------------------------------------------------------
// Linear attention, two-phase.
// Phase 1: partial KV[72] per (chunk, b, h).  Phase 2: sum + apply + pack.
// ---------------------------------------------------------------------------
#define CHPX (HW / NCHK)   // 512 pixels per chunk

__global__ __launch_bounds__(256)
void attn_kv_kernel()
{
    const int b  = blockIdx.y;
    const int h  = blockIdx.x;
    const int cz = blockIdx.z;
    const int t  = threadIdx.x;

    const float* base = (h < 64)
        ? g_qkv + ((size_t)b * QKVCH + h * 24) * HW
        : g_agg + ((size_t)b * QKVCH + (h - 64) * 24) * HW;

    float kv[72];
#pragma unroll
    for (int i = 0; i < 72; i++) kv[i] = 0.f;

#pragma unroll
    for (int it = 0; it < CHPX / 256; it++) {
        int p = cz * CHPX + it * 256 + t;
        float kd[8], ve[8];
#pragma unroll
        for (int d = 0; d < 8; d++) kd[d] = fmaxf(base[(size_t)(8 + d) * HW + p], 0.f);
#pragma unroll
        for (int e = 0; e < 8; e++) ve[e] = base[(size_t)(16 + e) * HW + p];
#pragma unroll
        for (int d = 0; d < 8; d++) {
#pragma unroll
            for (int e = 0; e < 8; e++) kv[d * 9 + e] = fmaf(kd[d], ve[e], kv[d * 9 + e]);
            kv[d * 9 + 8] += kd[d];
        }
    }

    __shared__ float red[8][72];
#pragma unroll
    for (int i = 0; i < 72; i++) {
        float v = kv[i];
        v += __shfl_xor_sync(0xffffffffu, v, 16);
        v += __shfl_xor_sync(0xffffffffu, v, 8);
        v += __shfl_xor_sync(0xffffffffu, v, 4);
        v += __shfl_xor_sync(0xffffffffu, v, 2);
        v += __shfl_xor_sync(0xffffffffu, v, 1);
        kv[i] = v;
    }
    const int lane = t & 31, wid = t >> 5;
    if (lane == 0) {
#pragma unroll
        for (int i = 0; i < 72; i++) red[wid][i] = kv[i];
    }
    __syncthreads();
    if (t < 72) {
        float s = 0.f;
#pragma unroll
        for (int w = 0; w < 8; w++) s += red[w][t];
        g_kvpart[cz][b][h][t] = s;
    }
}

__global__ __launch_bounds__(256)
void attn_apply_kernel()
{
    const int b  = blockIdx.y;
    const int h  = blockIdx.x;
    const int cz = blockIdx.z;
    const int t  = threadIdx.x;

    const float* base = (h < 64)
        ? g_qkv + ((size_t)b * QKVCH + h * 24) * HW
        : g_agg + ((size_t)b * QKVCH + (h - 64) * 24) * HW;

    __shared__ float kvf[72];
    if (t < 72) {
        float s = 0.f;
#pragma unroll
        for (int c = 0; c < NCHK; c++) s += g_kvpart[c][b][h][t];
        kvf[t] = s;
    }
    __syncthreads();

    uint32_t* dsth = g_atth + (size_t)b * HW * KWA + h * 4;
    uint32_t* dstl = g_attl + (size_t)b * HW * KWA + h * 4;
#pragma unroll
    for (int it = 0; it < CHPX / 256; it++) {
        int p = cz * CHPX + it * 256 + t;
        float qd[8];
#pragma unroll
        for (int d = 0; d < 8; d++) qd[d] = fmaxf(base[(size_t)d * HW + p], 0.f);
        float num[9];
#pragma unroll
        for (int e = 0; e < 9; e++) {
            float s = 0.f;
#pragma unroll
            for (int d = 0; d < 8; d++) s = fmaf(qd[d], kvf[d * 9 + e], s);
            num[e] = s;
        }
        float inv = 1.f / (num[8] + EPSV);
        uint32_t hw4[4], lw4[4];
#pragma unroll
        for (int j = 0; j < 4; j++) {
            uint16_t h0, l0, h1, l1;
            split_bf16(num[2 * j] * inv, h0, l0);
            split_bf16(num[2 * j + 1] * inv, h1, l1);
            hw4[j] = pack2(h0, h1);
            lw4[j] = pack2(l0, l1);
        }
        *(uint4*)(dsth + (size_t)p * KWA) = make_uint4(hw4[0], hw4[1], hw4[2], hw4[3]);
        *(uint4*)(dstl + (size_t)p * KWA) = make_uint4(lw4[0], lw4[1], lw4[2], lw4[3]);
    }
}

// ---------------------------------------------------------------------------
extern "C" void kernel_launch(void* const* d_in, const int* in_sizes, int n_in,
                              void* d_out, int out_size)
{
    const float* x       = (const float*)d_in[0];
    const float* w_qkv   = (const float*)d_in[1];
    const float* w_dw    = (const float*)d_in[2];
    const float* w_pw    = (const float*)d_in[3];
    const float* w_proj  = (const float*)d_in[4];
    const float* bn_g    = (const float*)d_in[5];
    const float* bn_b    = (const float*)d_in[6];
    const float* bn_m    = (const float*)d_in[7];
    const float* bn_v    = (const float*)d_in[8];
    float* out = (float*)d_out;

    float *qkv_p;
    uint32_t *xh_p, *xl_p, *ath_p, *atl_p, *wqh_p, *wql_p, *wph_p, *wpl_p;
    cudaGetSymbolAddress((void**)&qkv_p, g_qkv);
    cudaGetSymbolAddress((void**)&xh_p,  g_xh);
    cudaGetSymbolAddress((void**)&xl_p,  g_xl);
    cudaGetSymbolAddress((void**)&ath_p, g_atth);
    cudaGetSymbolAddress((void**)&atl_p, g_attl);
    cudaGetSymbolAddress((void**)&wqh_p, g_wqh);
    cudaGetSymbolAddress((void**)&wql_p, g_wql);
    cudaGetSymbolAddress((void**)&wph_p, g_wph);
    cudaGetSymbolAddress((void**)&wpl_p, g_wpl);

    cudaFuncSetAttribute(mma_gemm_kernel<false>,
                         cudaFuncAttributeMaxDynamicSharedMemorySize, SMEM_BYTES);
    cudaFuncSetAttribute(mma_gemm_kernel<true>,
                         cudaFuncAttributeMaxDynamicSharedMemorySize, SMEM_BYTES);

    // 0) pre-split weights + x
    presplit_w_kernel<<<(QKVCH * KWX + 255) / 256, 256>>>(
        w_qkv, wqh_p, wql_p, QKVCH * KWX);
    presplit_w_kernel<<<(CIN * KWA + 255) / 256, 256>>>(
        w_proj, wph_p, wpl_p, CIN * KWA);
    presplit_x_kernel<<<dim3(HW / 32, CIN / 128, NB), 256>>>(x, xh_p, xl_p);

    // 1) qkv = x @ w_qkv
    mma_gemm_kernel<false><<<dim3(128, QKVCH / 128), 256, SMEM_BYTES>>>(
        xh_p, xl_p, wqh_p, wql_p, qkv_p, CIN, QKVCH,
        nullptr, nullptr, nullptr, nullptr);

    // 2) depthwise 5x5 + grouped pointwise 8x8
    dwpw_kernel<<<dim3(HH / 8, NGROUP, NB), 256>>>(w_dw, w_pw);

    // 3) linear attention, two-phase
    attn_kv_kernel<<<dim3(NHEAD, NB, NCHK), 256>>>();
    attn_apply_kernel<<<dim3(NHEAD, NB, NCHK), 256>>>();

    // 4) proj GEMM + BN affine
    mma_gemm_kernel<true><<<dim3(128, CIN / 128), 256, SMEM_BYTES>>>(
        ath_p, atl_p, wph_p, wpl_p, out, ATTNCH, CIN,
        bn_g, bn_b, bn_m, bn_v);
}

// round 15
// speedup vs baseline: 1.0129x; 1.0129x over previous
#include <cuda_runtime.h>
#include <cuda_bf16.h>
#include <math.h>
#include <stdint.h>

// Problem constants
#define NB      4
#define CIN     512
#define HH      64
#define WW      64
#define HW      4096
#define QKVCH   1536
#define NGROUP  192
#define NHEAD   128
#define ATTNCH  1024
#define EPSV    1e-5f
#define BNEPS   1e-5f

#define KWX  (CIN / 2)
#define KWA  (ATTNCH / 2)

// Scratch
__device__ float g_qkv [(size_t)NB * QKVCH * HW];
__device__ float g_agg [(size_t)NB * QKVCH * HW];
__device__ uint32_t g_xh   [(size_t)NB * HW * KWX];
__device__ uint32_t g_xl   [(size_t)NB * HW * KWX];
__device__ uint32_t g_atth [(size_t)NB * HW * KWA];
__device__ uint32_t g_attl [(size_t)NB * HW * KWA];
__device__ uint32_t g_wqh  [QKVCH * KWX];
__device__ uint32_t g_wql  [QKVCH * KWX];
__device__ uint32_t g_wph  [CIN * KWA];
__device__ uint32_t g_wpl  [CIN * KWA];

// ===========================================================================
// Helpers
// ===========================================================================
__device__ __forceinline__ void split_bf16(float x, uint16_t& h, uint16_t& l) {
    __nv_bfloat16 hb = __float2bfloat16_rn(x);
    float r = x - __bfloat162float(hb);
    __nv_bfloat16 lb = __float2bfloat16_rn(r);
    h = __nv_bfloat16_raw(hb).x;
    l = __nv_bfloat16_raw(lb).x;
}
__device__ __forceinline__ uint32_t pack2(uint16_t lo16, uint16_t hi16) {
    return (uint32_t)lo16 | ((uint32_t)hi16 << 16);
}
__device__ __forceinline__ void mma_bf16(float d[4], const uint32_t a[4],
                                         uint32_t b0, uint32_t b1) {
    asm volatile(
        "mma.sync.aligned.m16n8k16.row.col.f32.bf16.bf16.f32 "
        "{%0,%1,%2,%3}, {%4,%5,%6,%7}, {%8,%9}, {%0,%1,%2,%3};\n"
        : "+f"(d[0]), "+f"(d[1]), "+f"(d[2]), "+f"(d[3])
        : "r"(a[0]), "r"(a[1]), "r"(a[2]), "r"(a[3]), "r"(b0), "r"(b1));
}
__device__ __forceinline__ void cpasync16(uint32_t* smem_dst, const uint32_t* gsrc) {
    uint32_t s = (uint32_t)__cvta_generic_to_shared(smem_dst);
    asm volatile("cp.async.ca.shared.global [%0], [%1], 16;" :: "r"(s), "l"(gsrc));
}
#define LDSM_X4(r, addr)                                                      \
    asm volatile("ldmatrix.sync.aligned.m8n8.x4.shared.b16 {%0,%1,%2,%3}, [%4];" \
        : "=r"((r)[0]), "=r"((r)[1]), "=r"((r)[2]), "=r"((r)[3]) : "r"(addr))

// ===========================================================================
// Pre-split kernels
// ===========================================================================
__global__ void presplit_w_kernel(const float* __restrict__ w,
                                  uint32_t* __restrict__ wh,
                                  uint32_t* __restrict__ wl, int nwords) {
    int i = blockIdx.x * blockDim.x + threadIdx.x;
    if (i >= nwords) return;
    float2 v = ((const float2*)w)[i];
    uint16_t h0, l0, h1, l1;
    split_bf16(v.x, h0, l0); split_bf16(v.y, h1, l1);
    wh[i] = pack2(h0, h1);
    wl[i] = pack2(l0, l1);
}
__global__ __launch_bounds__(256)
void presplit_x_kernel(const float* __restrict__ x,
                       uint32_t* __restrict__ xh,
                       uint32_t* __restrict__ xl) {
    __shared__ uint32_t th[64][33];
    __shared__ uint32_t tl[64][33];
    const int t   = threadIdx.x;
    const int b   = blockIdx.z;
    const int cp0 = blockIdx.y * 64;
    const int p0  = blockIdx.x * 32;

#pragma unroll
    for (int it = 0; it < 8; it++) {
        int cp = it * 8 + (t >> 5);
        int p  = t & 31;
        const float* s = x + ((size_t)(b * CIN + 2 * (cp0 + cp))) * HW + p0 + p;
        float a = s[0];
        float c = s[HW];
        uint16_t ha, la, hc, lc;
        split_bf16(a, ha, la); split_bf16(c, hc, lc);
        th[cp][p] = pack2(ha, hc);
        tl[cp][p] = pack2(la, lc);
    }
    __syncthreads();

#pragma unroll
    for (int it = 0; it < 2; it++) {
        int idx = t + it * 256;
        int p   = idx >> 4;
        int c4  = (idx & 15) * 4;
        uint4 hv = make_uint4(th[c4][p], th[c4 + 1][p], th[c4 + 2][p], th[c4 + 3][p]);
        uint4 lv = make_uint4(tl[c4][p], tl[c4 + 1][p], tl[c4 + 2][p], tl[c4 + 3][p]);
        size_t o = ((size_t)b * HW + p0 + p) * KWX + cp0 + c4;
        *(uint4*)(xh + o) = hv;
        *(uint4*)(xl + o) = lv;
    }
}

// ===========================================================================
// tensor GEMM, 2-stage cp.async pipeline; all fragments loaded up front
// per k16-step so LDSM latency overlaps the MMA chain.
// ===========================================================================
#define STRIDE20 20
#define ST_AH 0
#define ST_AL 2560
#define ST_BH 5120
#define ST_BL 7680
#define ST_WORDS 10240
#define SMEM_BYTES (2 * ST_WORDS * 4)

__device__ __forceinline__ void stage_tile(uint32_t* sbase, int t, int KW,
                                           const uint32_t* ahr, const uint32_t* alr,
                                           const uint32_t* bhr, const uint32_t* blr) {
#pragma unroll
    for (int r = 0; r < 2; r++) {
        int id = t + r * 256, o = id >> 2, c4 = (id & 3) * 4;
        cpasync16(sbase + ST_AH + o * STRIDE20 + c4, ahr + (size_t)o * KW + c4);
        cpasync16(sbase + ST_AL + o * STRIDE20 + c4, alr + (size_t)o * KW + c4);
    }
#pragma unroll
    for (int r = 0; r < 2; r++) {
        int id = t + r * 256, n = id >> 2, c4 = (id & 3) * 4;
        cpasync16(sbase + ST_BH + n * STRIDE20 + c4, bhr + (size_t)n * KW + c4);
        cpasync16(sbase + ST_BL + n * STRIDE20 + c4, blr + (size_t)n * KW + c4);
    }
    asm volatile("cp.async.commit_group;" ::: "memory");
}

template <bool BN>
__global__ __launch_bounds__(256, 2)
void mma_gemm_kernel(const uint32_t* __restrict__ Bh_g,
                     const uint32_t* __restrict__ Bl_g,
                     const uint32_t* __restrict__ Ah_g,
                     const uint32_t* __restrict__ Al_g,
                     float* __restrict__ C, int K, int Ochan,
                     const float* __restrict__ bn_gamma,
                     const float* __restrict__ bn_beta,
                     const float* __restrict__ bn_mean,
                     const float* __restrict__ bn_var)
{
    extern __shared__ uint32_t smw[];
    const int KW = K >> 1;
    const int t = threadIdx.x, lane = t & 31, wid = t >> 5;
    const int wm = wid & 3, wn = wid >> 2;
    const int bx = blockIdx.x;
    const int b  = bx >> 5;
    const int p0 = (bx & 31) * 128;
    const int o0 = blockIdx.y * 128;

    const uint32_t* Bhb = Bh_g + ((size_t)b * HW + p0) * KW;
    const uint32_t* Blb = Bl_g + ((size_t)b * HW + p0) * KW;
    const uint32_t* Ahb = Ah_g + (size_t)o0 * KW;
    const uint32_t* Alb = Al_g + (size_t)o0 * KW;

    uint32_t aoff[2];
#pragma unroll
    for (int i = 0; i < 2; i++)
        aoff[i] = ((wm * 32 + i * 16 + (lane & 15)) * STRIDE20 +
                   ((lane >> 4) & 1) * 4) * 4;
    uint32_t boff[4];
#pragma unroll
    for (int jj = 0; jj < 4; jj++)
        boff[jj] = ((wn * 64 + jj * 16 + (lane & 7) + ((lane >> 4) & 1) * 8) * STRIDE20 +
                    ((lane >> 3) & 1) * 4) * 4;

    const uint32_t smem32 = (uint32_t)__cvta_generic_to_shared(smw);

    float acc[2][8][4];
#pragma unroll
    for (int i = 0; i < 2; i++)
#pragma unroll
        for (int j = 0; j < 8; j++)
#pragma unroll
            for (int e = 0; e < 4; e++) acc[i][j][e] = 0.f;

    const int NT = K / 32;
    stage_tile(smw, t, KW, Ahb, Alb, Bhb, Blb);

    for (int kt = 0; kt < NT; kt++) {
        if (kt + 1 < NT) {
            int kw0 = (kt + 1) * 16;
            stage_tile(smw + ((kt + 1) & 1) * ST_WORDS, t, KW,
                       Ahb + kw0, Alb + kw0, Bhb + kw0, Blb + kw0);
            asm volatile("cp.async.wait_group 1;" ::: "memory");
        } else {
            asm volatile("cp.async.wait_group 0;" ::: "memory");
        }
        __syncthreads();

        const uint32_t sb = smem32 + ((kt & 1) ? ST_WORDS * 4 : 0);

#pragma unroll
        for (int s = 0; s < 2; s++) {
            const uint32_t sd = s * 32;
            uint32_t ah[2][4], al[2][4], bh[4][4], bl[4][4];
            // Load ALL fragments first: 12 independent LDSM, then 48 MMAs.
#pragma unroll
            for (int i = 0; i < 2; i++) {
                LDSM_X4(ah[i], sb + ST_AH * 4 + aoff[i] + sd);
                LDSM_X4(al[i], sb + ST_AL * 4 + aoff[i] + sd);
            }
#pragma unroll
            for (int jj = 0; jj < 4; jj++) {
                LDSM_X4(bh[jj], sb + ST_BH * 4 + boff[jj] + sd);
                LDSM_X4(bl[jj], sb + ST_BL * 4 + boff[jj] + sd);
            }
#pragma unroll
            for (int jj = 0; jj < 4; jj++)
#pragma unroll
                for (int h = 0; h < 2; h++) {
                    int j = 2 * jj + h;
                    uint32_t bh0 = bh[jj][2 * h], bh1 = bh[jj][2 * h + 1];
                    uint32_t bl0 = bl[jj][2 * h], bl1 = bl[jj][2 * h + 1];
#pragma unroll
                    for (int i = 0; i < 2; i++) {
                        mma_bf16(acc[i][j], ah[i], bh0, bh1);
                        mma_bf16(acc[i][j], al[i], bh0, bh1);
                        mma_bf16(acc[i][j], ah[i], bl0, bl1);
                    }
                }
        }
        __syncthreads();
    }

    const int orow = o0 + wm * 32 + (lane >> 2);
    float scl[4], bia[4];
#pragma unroll
    for (int r = 0; r < 4; r++) {
        if (BN) {
            int o = orow + 8 * r;
            float inv = bn_gamma[o] * rsqrtf(bn_var[o] + BNEPS);
            scl[r] = inv;
            bia[r] = bn_beta[o] - bn_mean[o] * inv;
        } else { scl[r] = 1.f; bia[r] = 0.f; }
    }
    float* Cb = C + (size_t)b * Ochan * HW;
    const int pbase = p0 + wn * 64 + (lane & 3) * 2;
#pragma unroll
    for (int i = 0; i < 2; i++) {
        int oA = orow + 16 * i;
        int r0 = 2 * i;
#pragma unroll
        for (int j = 0; j < 8; j++) {
            int p = pbase + 8 * j;
            float2 v0, v1;
            v0.x = acc[i][j][0] * scl[r0] + bia[r0];
            v0.y = acc[i][j][1] * scl[r0] + bia[r0];
            v1.x = acc[i][j][2] * scl[r0 + 1] + bia[r0 + 1];
            v1.y = acc[i][j][3] * scl[r0 + 1] + bia[r0 + 1];
            *(float2*)&Cb[(size_t)oA * HW + p]       = v0;
            *(float2*)&Cb[(size_t)(oA + 8) * HW + p] = v1;
        }
    }
}

// ---------------------------------------------------------------------------
// Fused depthwise 5x5 + grouped 8x8 pointwise — register sliding window.
// ---------------------------------------------------------------------------
__global__ __launch_bounds__(256)
void dwpw_kernel(const float* __restrict__ w_dw,
                 const float* __restrict__ w_pw)
{
    const int b  = blockIdx.z;
    const int g  = blockIdx.y;
    const int r0 = blockIdx.x * 8;
    const int t  = threadIdx.x;

    __shared__ float sin_[8][12][68];
    __shared__ float sdw[8][8][68];
    __shared__ float swdw[8][25];
    __shared__ float swpw[64];

    const float* src = g_qkv + ((size_t)b * QKVCH + g * 8) * HW;
    float*       dst = g_agg + ((size_t)b * QKVCH + g * 8) * HW;

    if (t < 200) swdw[t / 25][t % 25] = w_dw[(size_t)(g * 8 + t / 25) * 25 + (t % 25)];
    if (t < 64)  swpw[t] = w_pw[(size_t)g * 64 + t];

    for (int idx = t; idx < 8 * 12 * 68; idx += 256) {
        int i   = idx / (12 * 68);
        int rem = idx % (12 * 68);
        int rr  = rem / 68, cc = rem % 68;
        int gr  = r0 + rr - 2, gc = cc - 2;
        float v = 0.f;
        if (gr >= 0 && gr < HH && gc >= 0 && gc < WW)
            v = src[(size_t)i * HW + gr * WW + gc];
        sin_[i][rr][cc] = v;
    }
    __syncthreads();

#pragma unroll
    for (int j = 0; j < 2; j++) {
        int task = t + j * 256;
        int cs = task & 7, rr = (task >> 3) & 7, i = task >> 6;
        float acc0[8];
#pragma unroll
        for (int k = 0; k < 8; k++) acc0[k] = 0.f;
#pragma unroll
        for (int dy = 0; dy < 5; dy++) {
            const float* row = &sin_[i][rr + dy][cs * 8];
            float rbuf[12];
            *(float4*)&rbuf[0] = *(const float4*)&row[0];
            *(float4*)&rbuf[4] = *(const float4*)&row[4];
            *(float4*)&rbuf[8] = *(const float4*)&row[8];
#pragma unroll
            for (int dx = 0; dx < 5; dx++) {
                float wv = swdw[i][dy * 5 + dx];
#pragma unroll
                for (int k = 0; k < 8; k++)
                    acc0[k] = fmaf(rbuf[k + dx], wv, acc0[k]);
            }
        }
        *(float4*)&sdw[i][rr][cs * 8]     = make_float4(acc0[0], acc0[1], acc0[2], acc0[3]);
        *(float4*)&sdw[i][rr][cs * 8 + 4] = make_float4(acc0[4], acc0[5], acc0[6], acc0[7]);
    }
    __syncthreads();

#pragma unroll
    for (int j = 0; j < 2; j++) {
        int task = t + j * 256;
        int cs = task & 7, rr = (task >> 3) & 7, o = task >> 6;
        float acc0[8];
#pragma unroll
        for (int k = 0; k < 8; k++) acc0[k] = 0.f;
#pragma unroll
        for (int i = 0; i < 8; i++) {
            float wv = swpw[o * 8 + i];
            float rbuf[8];
            *(float4*)&rbuf[0] = *(const float4*)&sdw[i][rr][cs * 8];
            *(float4*)&rbuf[4] = *(const float4*)&sdw[i][rr][cs * 8 + 4];
#pragma unroll
            for (int k = 0; k < 8; k++)
                acc0[k] = fmaf(rbuf[k], wv, acc0[k]);
        }
        float* dp = dst + (size_t)o * HW + (r0 + rr) * WW + cs * 8;
        *(float4*)&dp[0] = make_float4(acc0[0], acc0[1], acc0[2], acc0[3]);
        *(float4*)&dp[4] = make_float4(acc0[4], acc0[5], acc0[6], acc0[7]);
    }
}

// ---------------------------------------------------------------------------
// Linear attention per (batch, head) — single phase (R12 version).
// ---------------------------------------------------------------------------
__global__ __launch_bounds__(256)
void attn_kernel()
{
    const int b = blockIdx.y;
    const int h = blockIdx.x;
    const int t = threadIdx.x;

    const float* base = (h < 64)
        ? g_qkv + ((size_t)b * QKVCH + h * 24) * HW
        : g_agg + ((size_t)b * QKVCH + (h - 64) * 24) * HW;

    float kv[72];
#pragma unroll
    for (int i = 0; i < 72; i++) kv[i] = 0.f;

    for (int p = t; p < HW; p += 256) {
        float kd[8], ve[8];
#pragma unroll
        for (int d = 0; d < 8; d++) kd[d] = fmaxf(base[(size_t)(8 + d) * HW + p], 0.f);
#pragma unroll
        for (int e = 0; e < 8; e++) ve[e] = base[(size_t)(16 + e) * HW + p];
#pragma unroll
        for (int d = 0; d < 8; d++) {
#pragma unroll
            for (int e = 0; e < 8; e++) kv[d * 9 + e] = fmaf(kd[d], ve[e], kv[d * 9 + e]);
            kv[d * 9 + 8] += kd[d];
        }
    }

    __shared__ float red[8][72];
    __shared__ float kvf[72];
#pragma unroll
    for (int i = 0; i < 72; i++) {
        float v = kv[i];
        v += __shfl_xor_sync(0xffffffffu, v, 16);
        v += __shfl_xor_sync(0xffffffffu, v, 8);
        v += __shfl_xor_sync(0xffffffffu, v, 4);
        v += __shfl_xor_sync(0xffffffffu, v, 2);
        v += __shfl_xor_sync(0xffffffffu, v, 1);
        kv[i] = v;
    }
    const int lane = t & 31, wid = t >> 5;
    if (lane == 0) {
#pragma unroll
        for (int i = 0; i < 72; i++) red[wid][i] = kv[i];
    }
    __syncthreads();
    if (t < 72) {
        float s = 0.f;
#pragma unroll
        for (int w = 0; w < 8; w++) s += red[w][t];
        kvf[t] = s;
    }
    __syncthreads();

    uint32_t* dsth = g_atth + (size_t)b * HW * KWA + h * 4;
    uint32_t* dstl = g_attl + (size_t)b * HW * KWA + h * 4;
    for (int p = t; p < HW; p += 256) {
        float qd[8];
#pragma unroll
        for (int d = 0; d < 8; d++) qd[d] = fmaxf(base[(size_t)d * HW + p], 0.f);
        float num[9];
#pragma unroll
        for (int e = 0; e < 9; e++) {
            float s = 0.f;
#pragma unroll
            for (int d = 0; d < 8; d++) s = fmaf(qd[d], kvf[d * 9 + e], s);
            num[e] = s;
        }
        float inv = 1.f / (num[8] + EPSV);
        uint32_t hw4[4], lw4[4];
#pragma unroll
        for (int j = 0; j < 4; j++) {
            uint16_t h0, l0, h1, l1;
            split_bf16(num[2 * j] * inv, h0, l0);
            split_bf16(num[2 * j + 1] * inv, h1, l1);
            hw4[j] = pack2(h0, h1);
            lw4[j] = pack2(l0, l1);
        }
        *(uint4*)(dsth + (size_t)p * KWA) = make_uint4(hw4[0], hw4[1], hw4[2], hw4[3]);
        *(uint4*)(dstl + (size_t)p * KWA) = make_uint4(lw4[0], lw4[1], lw4[2], lw4[3]);
    }
}

// ---------------------------------------------------------------------------
extern "C" void kernel_launch(void* const* d_in, const int* in_sizes, int n_in,
                              void* d_out, int out_size)
{
    const float* x       = (const float*)d_in[0];
    const float* w_qkv   = (const float*)d_in[1];
    const float* w_dw    = (const float*)d_in[2];
    const float* w_pw    = (const float*)d_in[3];
    const float* w_proj  = (const float*)d_in[4];
    const float* bn_g    = (const float*)d_in[5];
    const float* bn_b    = (const float*)d_in[6];
    const float* bn_m    = (const float*)d_in[7];
    const float* bn_v    = (const float*)d_in[8];
    float* out = (float*)d_out;

    float *qkv_p;
    uint32_t *xh_p, *xl_p, *ath_p, *atl_p, *wqh_p, *wql_p, *wph_p, *wpl_p;
    cudaGetSymbolAddress((void**)&qkv_p, g_qkv);
    cudaGetSymbolAddress((void**)&xh_p,  g_xh);
    cudaGetSymbolAddress((void**)&xl_p,  g_xl);
    cudaGetSymbolAddress((void**)&ath_p, g_atth);
    cudaGetSymbolAddress((void**)&atl_p, g_attl);
    cudaGetSymbolAddress((void**)&wqh_p, g_wqh);
    cudaGetSymbolAddress((void**)&wql_p, g_wql);
    cudaGetSymbolAddress((void**)&wph_p, g_wph);
    cudaGetSymbolAddress((void**)&wpl_p, g_wpl);

    cudaFuncSetAttribute(mma_gemm_kernel<false>,
                         cudaFuncAttributeMaxDynamicSharedMemorySize, SMEM_BYTES);
    cudaFuncSetAttribute(mma_gemm_kernel<true>,
                         cudaFuncAttributeMaxDynamicSharedMemorySize, SMEM_BYTES);

    // 0) pre-split weights + x
    presplit_w_kernel<<<(QKVCH * KWX + 255) / 256, 256>>>(
        w_qkv, wqh_p, wql_p, QKVCH * KWX);
    presplit_w_kernel<<<(CIN * KWA + 255) / 256, 256>>>(
        w_proj, wph_p, wpl_p, CIN * KWA);
    presplit_x_kernel<<<dim3(HW / 32, CIN / 128, NB), 256>>>(x, xh_p, xl_p);

    // 1) qkv = x @ w_qkv
    mma_gemm_kernel<false><<<dim3(128, QKVCH / 128), 256, SMEM_BYTES>>>(
        xh_p, xl_p, wqh_p, wql_p, qkv_p, CIN, QKVCH,
        nullptr, nullptr, nullptr, nullptr);

    // 2) depthwise 5x5 + grouped pointwise 8x8
    dwpw_kernel<<<dim3(HH / 8, NGROUP, NB), 256>>>(w_dw, w_pw);

    // 3) linear attention (single phase)
    attn_kernel<<<dim3(NHEAD, NB), 256>>>();

    // 4) proj GEMM + BN affine
    mma_gemm_kernel<true><<<dim3(128, CIN / 128), 256, SMEM_BYTES>>>(
        ath_p, atl_p, wph_p, wpl_p, out, ATTNCH, CIN,
        bn_g, bn_b, bn_m, bn_v);
}

// round 17
// speedup vs baseline: 1.0612x; 1.0477x over previous
#include <cuda_runtime.h>
#include <cuda_bf16.h>
#include <math.h>
#include <stdint.h>

// Problem constants
#define NB      4
#define CIN     512
#define HH      64
#define WW      64
#define HW      4096
#define QKVCH   1536
#define NGROUP  192
#define NHEAD   128
#define ATTNCH  1024
#define EPSV    1e-5f
#define BNEPS   1e-5f

#define KWX  (CIN / 2)
#define KWA  (ATTNCH / 2)

// Scratch
__device__ float g_qkv [(size_t)NB * QKVCH * HW];
__device__ float g_agg [(size_t)NB * QKVCH * HW];
__device__ uint32_t g_xh   [(size_t)NB * HW * KWX];
__device__ uint32_t g_xl   [(size_t)NB * HW * KWX];
__device__ uint32_t g_atth [(size_t)NB * HW * KWA];
__device__ uint32_t g_attl [(size_t)NB * HW * KWA];
__device__ uint32_t g_wqh  [QKVCH * KWX];
__device__ uint32_t g_wql  [QKVCH * KWX];
__device__ uint32_t g_wph  [CIN * KWA];
__device__ uint32_t g_wpl  [CIN * KWA];

// ===========================================================================
// Helpers
// ===========================================================================
__device__ __forceinline__ void split_bf16(float x, uint16_t& h, uint16_t& l) {
    __nv_bfloat16 hb = __float2bfloat16_rn(x);
    float r = x - __bfloat162float(hb);
    __nv_bfloat16 lb = __float2bfloat16_rn(r);
    h = __nv_bfloat16_raw(hb).x;
    l = __nv_bfloat16_raw(lb).x;
}
__device__ __forceinline__ uint32_t pack2(uint16_t lo16, uint16_t hi16) {
    return (uint32_t)lo16 | ((uint32_t)hi16 << 16);
}
__device__ __forceinline__ void mma_bf16(float d[4], const uint32_t a[4],
                                         uint32_t b0, uint32_t b1) {
    asm volatile(
        "mma.sync.aligned.m16n8k16.row.col.f32.bf16.bf16.f32 "
        "{%0,%1,%2,%3}, {%4,%5,%6,%7}, {%8,%9}, {%0,%1,%2,%3};\n"
        : "+f"(d[0]), "+f"(d[1]), "+f"(d[2]), "+f"(d[3])
        : "r"(a[0]), "r"(a[1]), "r"(a[2]), "r"(a[3]), "r"(b0), "r"(b1));
}
__device__ __forceinline__ void cpasync16(uint32_t* smem_dst, const uint32_t* gsrc) {
    uint32_t s = (uint32_t)__cvta_generic_to_shared(smem_dst);
    asm volatile("cp.async.ca.shared.global [%0], [%1], 16;" :: "r"(s), "l"(gsrc));
}
#define LDSM_X4(r, addr)                                                      \
    asm volatile("ldmatrix.sync.aligned.m8n8.x4.shared.b16 {%0,%1,%2,%3}, [%4];" \
        : "=r"((r)[0]), "=r"((r)[1]), "=r"((r)[2]), "=r"((r)[3]) : "r"(addr))

// ===========================================================================
// Pre-split kernels
// ===========================================================================
// Both weight tensors in one launch.
__global__ void presplit_w_kernel(const float* __restrict__ w1,
                                  uint32_t* __restrict__ wh1,
                                  uint32_t* __restrict__ wl1, int n1,
                                  const float* __restrict__ w2,
                                  uint32_t* __restrict__ wh2,
                                  uint32_t* __restrict__ wl2, int n2) {
    int i = blockIdx.x * blockDim.x + threadIdx.x;
    const float* w; uint32_t *wh, *wl; int idx;
    if (i < n1) { w = w1; wh = wh1; wl = wl1; idx = i; }
    else if (i < n1 + n2) { w = w2; wh = wh2; wl = wl2; idx = i - n1; }
    else return;
    float2 v = ((const float2*)w)[idx];
    uint16_t h0, l0, h1, l1;
    split_bf16(v.x, h0, l0); split_bf16(v.y, h1, l1);
    wh[idx] = pack2(h0, h1);
    wl[idx] = pack2(l0, l1);
}
__global__ __launch_bounds__(256)
void presplit_x_kernel(const float* __restrict__ x,
                       uint32_t* __restrict__ xh,
                       uint32_t* __restrict__ xl) {
    __shared__ uint32_t th[64][33];
    __shared__ uint32_t tl[64][33];
    const int t   = threadIdx.x;
    const int b   = blockIdx.z;
    const int cp0 = blockIdx.y * 64;
    const int p0  = blockIdx.x * 32;

#pragma unroll
    for (int it = 0; it < 8; it++) {
        int cp = it * 8 + (t >> 5);
        int p  = t & 31;
        const float* s = x + ((size_t)(b * CIN + 2 * (cp0 + cp))) * HW + p0 + p;
        float a = s[0];
        float c = s[HW];
        uint16_t ha, la, hc, lc;
        split_bf16(a, ha, la); split_bf16(c, hc, lc);
        th[cp][p] = pack2(ha, hc);
        tl[cp][p] = pack2(la, lc);
    }
    __syncthreads();

#pragma unroll
    for (int it = 0; it < 2; it++) {
        int idx = t + it * 256;
        int p   = idx >> 4;
        int c4  = (idx & 15) * 4;
        uint4 hv = make_uint4(th[c4][p], th[c4 + 1][p], th[c4 + 2][p], th[c4 + 3][p]);
        uint4 lv = make_uint4(tl[c4][p], tl[c4 + 1][p], tl[c4 + 2][p], tl[c4 + 3][p]);
        size_t o = ((size_t)b * HW + p0 + p) * KWX + cp0 + c4;
        *(uint4*)(xh + o) = hv;
        *(uint4*)(xl + o) = lv;
    }
}

// ===========================================================================
// tensor GEMM — exact R12 structure (measured-best total).
// ===========================================================================
#define STRIDE20 20
#define ST_AH 0
#define ST_AL 2560
#define ST_BH 5120
#define ST_BL 7680
#define ST_WORDS 10240
#define SMEM_BYTES (2 * ST_WORDS * 4)

__device__ __forceinline__ void stage_tile(uint32_t* sbase, int t, int KW,
                                           const uint32_t* ahr, const uint32_t* alr,
                                           const uint32_t* bhr, const uint32_t* blr) {
#pragma unroll
    for (int r = 0; r < 2; r++) {
        int id = t + r * 256, o = id >> 2, c4 = (id & 3) * 4;
        cpasync16(sbase + ST_AH + o * STRIDE20 + c4, ahr + (size_t)o * KW + c4);
        cpasync16(sbase + ST_AL + o * STRIDE20 + c4, alr + (size_t)o * KW + c4);
    }
#pragma unroll
    for (int r = 0; r < 2; r++) {
        int id = t + r * 256, n = id >> 2, c4 = (id & 3) * 4;
        cpasync16(sbase + ST_BH + n * STRIDE20 + c4, bhr + (size_t)n * KW + c4);
        cpasync16(sbase + ST_BL + n * STRIDE20 + c4, blr + (size_t)n * KW + c4);
    }
    asm volatile("cp.async.commit_group;" ::: "memory");
}

template <bool BN>
__global__ __launch_bounds__(256, 2)
void mma_gemm_kernel(const uint32_t* __restrict__ Bh_g,
                     const uint32_t* __restrict__ Bl_g,
                     const uint32_t* __restrict__ Ah_g,
                     const uint32_t* __restrict__ Al_g,
                     float* __restrict__ C, int K, int Ochan,
                     const float* __restrict__ bn_gamma,
                     const float* __restrict__ bn_beta,
                     const float* __restrict__ bn_mean,
                     const float* __restrict__ bn_var)
{
    extern __shared__ uint32_t smw[];
    const int KW = K >> 1;
    const int t = threadIdx.x, lane = t & 31, wid = t >> 5;
    const int wm = wid & 3, wn = wid >> 2;
    const int bx = blockIdx.x;
    const int b  = bx >> 5;
    const int p0 = (bx & 31) * 128;
    const int o0 = blockIdx.y * 128;

    const uint32_t* Bhb = Bh_g + ((size_t)b * HW + p0) * KW;
    const uint32_t* Blb = Bl_g + ((size_t)b * HW + p0) * KW;
    const uint32_t* Ahb = Ah_g + (size_t)o0 * KW;
    const uint32_t* Alb = Al_g + (size_t)o0 * KW;

    uint32_t aoff[2];
#pragma unroll
    for (int i = 0; i < 2; i++)
        aoff[i] = ((wm * 32 + i * 16 + (lane & 15)) * STRIDE20 +
                   ((lane >> 4) & 1) * 4) * 4;
    uint32_t boff[4];
#pragma unroll
    for (int jj = 0; jj < 4; jj++)
        boff[jj] = ((wn * 64 + jj * 16 + (lane & 7) + ((lane >> 4) & 1) * 8) * STRIDE20 +
                    ((lane >> 3) & 1) * 4) * 4;

    const uint32_t smem32 = (uint32_t)__cvta_generic_to_shared(smw);

    float acc[2][8][4];
#pragma unroll
    for (int i = 0; i < 2; i++)
#pragma unroll
        for (int j = 0; j < 8; j++)
#pragma unroll
            for (int e = 0; e < 4; e++) acc[i][j][e] = 0.f;

    const int NT = K / 32;
    stage_tile(smw, t, KW, Ahb, Alb, Bhb, Blb);

    for (int kt = 0; kt < NT; kt++) {
        asm volatile("cp.async.wait_group 0;" ::: "memory");
        __syncthreads();

        if (kt + 1 < NT) {
            int kw0 = (kt + 1) * 16;
            stage_tile(smw + ((kt + 1) & 1) * ST_WORDS, t, KW,
                       Ahb + kw0, Alb + kw0, Bhb + kw0, Blb + kw0);
        }

        const uint32_t sb = smem32 + ((kt & 1) ? ST_WORDS * 4 : 0);

#pragma unroll
        for (int s = 0; s < 2; s++) {
            const uint32_t sd = s * 32;
            uint32_t ah[2][4], al[2][4], bb[4][4];
#pragma unroll
            for (int i = 0; i < 2; i++) {
                LDSM_X4(ah[i], sb + ST_AH * 4 + aoff[i] + sd);
                LDSM_X4(al[i], sb + ST_AL * 4 + aoff[i] + sd);
            }
#pragma unroll
            for (int jj = 0; jj < 4; jj++)
                LDSM_X4(bb[jj], sb + ST_BH * 4 + boff[jj] + sd);
#pragma unroll
            for (int jj = 0; jj < 4; jj++)
#pragma unroll
                for (int h = 0; h < 2; h++) {
                    int j = 2 * jj + h;
                    uint32_t b0 = bb[jj][2 * h], b1 = bb[jj][2 * h + 1];
#pragma unroll
                    for (int i = 0; i < 2; i++) {
                        mma_bf16(acc[i][j], ah[i], b0, b1);
                        mma_bf16(acc[i][j], al[i], b0, b1);
                    }
                }
#pragma unroll
            for (int jj = 0; jj < 4; jj++)
                LDSM_X4(bb[jj], sb + ST_BL * 4 + boff[jj] + sd);
#pragma unroll
            for (int jj = 0; jj < 4; jj++)
#pragma unroll
                for (int h = 0; h < 2; h++) {
                    int j = 2 * jj + h;
                    uint32_t b0 = bb[jj][2 * h], b1 = bb[jj][2 * h + 1];
#pragma unroll
                    for (int i = 0; i < 2; i++)
                        mma_bf16(acc[i][j], ah[i], b0, b1);
                }
        }
    }

    const int orow = o0 + wm * 32 + (lane >> 2);
    float scl[4], bia[4];
#pragma unroll
    for (int r = 0; r < 4; r++) {
        if (BN) {
            int o = orow + 8 * r;
            float inv = bn_gamma[o] * rsqrtf(bn_var[o] + BNEPS);
            scl[r] = inv;
            bia[r] = bn_beta[o] - bn_mean[o] * inv;
        } else { scl[r] = 1.f; bia[r] = 0.f; }
    }
    float* Cb = C + (size_t)b * Ochan * HW;
    const int pbase = p0 + wn * 64 + (lane & 3) * 2;
#pragma unroll
    for (int i = 0; i < 2; i++) {
        int oA = orow + 16 * i;
        int r0 = 2 * i;
#pragma unroll
        for (int j = 0; j < 8; j++) {
            int p = pbase + 8 * j;
            float2 v0, v1;
            v0.x = acc[i][j][0] * scl[r0] + bia[r0];
            v0.y = acc[i][j][1] * scl[r0] + bia[r0];
            v1.x = acc[i][j][2] * scl[r0 + 1] + bia[r0 + 1];
            v1.y = acc[i][j][3] * scl[r0 + 1] + bia[r0 + 1];
            *(float2*)&Cb[(size_t)oA * HW + p]       = v0;
            *(float2*)&Cb[(size_t)(oA + 8) * HW + p] = v1;
        }
    }
}

// ---------------------------------------------------------------------------
// Fused depthwise 5x5 + grouped 8x8 pointwise — register sliding window.
// ---------------------------------------------------------------------------
__global__ __launch_bounds__(256)
void dwpw_kernel(const float* __restrict__ w_dw,
                 const float* __restrict__ w_pw)
{
    const int b  = blockIdx.z;
    const int g  = blockIdx.y;
    const int r0 = blockIdx.x * 8;
    const int t  = threadIdx.x;

    __shared__ float sin_[8][12][68];
    __shared__ float sdw[8][8][68];
    __shared__ float swdw[8][25];
    __shared__ float swpw[64];

    const float* src = g_qkv + ((size_t)b * QKVCH + g * 8) * HW;
    float*       dst = g_agg + ((size_t)b * QKVCH + g * 8) * HW;

    if (t < 200) swdw[t / 25][t % 25] = w_dw[(size_t)(g * 8 + t / 25) * 25 + (t % 25)];
    if (t < 64)  swpw[t] = w_pw[(size_t)g * 64 + t];

    for (int idx = t; idx < 8 * 12 * 68; idx += 256) {
        int i   = idx / (12 * 68);
        int rem = idx % (12 * 68);
        int rr  = rem / 68, cc = rem % 68;
        int gr  = r0 + rr - 2, gc = cc - 2;
        float v = 0.f;
        if (gr >= 0 && gr < HH && gc >= 0 && gc < WW)
            v = src[(size_t)i * HW + gr * WW + gc];
        sin_[i][rr][cc] = v;
    }
    __syncthreads();

#pragma unroll
    for (int j = 0; j < 2; j++) {
        int task = t + j * 256;
        int cs = task & 7, rr = (task >> 3) & 7, i = task >> 6;
        float acc0[8];
#pragma unroll
        for (int k = 0; k < 8; k++) acc0[k] = 0.f;
#pragma unroll
        for (int dy = 0; dy < 5; dy++) {
            const float* row = &sin_[i][rr + dy][cs * 8];
            float rbuf[12];
            *(float4*)&rbuf[0] = *(const float4*)&row[0];
            *(float4*)&rbuf[4] = *(const float4*)&row[4];
            *(float4*)&rbuf[8] = *(const float4*)&row[8];
#pragma unroll
            for (int dx = 0; dx < 5; dx++) {
                float wv = swdw[i][dy * 5 + dx];
#pragma unroll
                for (int k = 0; k < 8; k++)
                    acc0[k] = fmaf(rbuf[k + dx], wv, acc0[k]);
            }
        }
        *(float4*)&sdw[i][rr][cs * 8]     = make_float4(acc0[0], acc0[1], acc0[2], acc0[3]);
        *(float4*)&sdw[i][rr][cs * 8 + 4] = make_float4(acc0[4], acc0[5], acc0[6], acc0[7]);
    }
    __syncthreads();

#pragma unroll
    for (int j = 0; j < 2; j++) {
        int task = t + j * 256;
        int cs = task & 7, rr = (task >> 3) & 7, o = task >> 6;
        float acc0[8];
#pragma unroll
        for (int k = 0; k < 8; k++) acc0[k] = 0.f;
#pragma unroll
        for (int i = 0; i < 8; i++) {
            float wv = swpw[o * 8 + i];
            float rbuf[8];
            *(float4*)&rbuf[0] = *(const float4*)&sdw[i][rr][cs * 8];
            *(float4*)&rbuf[4] = *(const float4*)&sdw[i][rr][cs * 8 + 4];
#pragma unroll
            for (int k = 0; k < 8; k++)
                acc0[k] = fmaf(rbuf[k], wv, acc0[k]);
        }
        float* dp = dst + (size_t)o * HW + (r0 + rr) * WW + cs * 8;
        *(float4*)&dp[0] = make_float4(acc0[0], acc0[1], acc0[2], acc0[3]);
        *(float4*)&dp[4] = make_float4(acc0[4], acc0[5], acc0[6], acc0[7]);
    }
}

// ---------------------------------------------------------------------------
// Linear attention per (batch, head) — single phase, float2 vector loads.
// ---------------------------------------------------------------------------
__global__ __launch_bounds__(256)
void attn_kernel()
{
    const int b = blockIdx.y;
    const int h = blockIdx.x;
    const int t = threadIdx.x;

    const float* base = (h < 64)
        ? g_qkv + ((size_t)b * QKVCH + h * 24) * HW
        : g_agg + ((size_t)b * QKVCH + (h - 64) * 24) * HW;

    float kv[72];
#pragma unroll
    for (int i = 0; i < 72; i++) kv[i] = 0.f;

#pragma unroll
    for (int it = 0; it < HW / 512; it++) {
        int p = (it * 256 + t) * 2;
        float2 kd[8], ve[8];
#pragma unroll
        for (int d = 0; d < 8; d++) {
            float2 v = *(const float2*)&base[(size_t)(8 + d) * HW + p];
            kd[d].x = fmaxf(v.x, 0.f);
            kd[d].y = fmaxf(v.y, 0.f);
        }
#pragma unroll
        for (int e = 0; e < 8; e++)
            ve[e] = *(const float2*)&base[(size_t)(16 + e) * HW + p];
#pragma unroll
        for (int d = 0; d < 8; d++) {
#pragma unroll
            for (int e = 0; e < 8; e++)
                kv[d * 9 + e] = fmaf(kd[d].x, ve[e].x,
                                fmaf(kd[d].y, ve[e].y, kv[d * 9 + e]));
            kv[d * 9 + 8] += kd[d].x + kd[d].y;
        }
    }

    __shared__ float red[8][72];
    __shared__ float kvf[72];
#pragma unroll
    for (int i = 0; i < 72; i++) {
        float v = kv[i];
        v += __shfl_xor_sync(0xffffffffu, v, 16);
        v += __shfl_xor_sync(0xffffffffu, v, 8);
        v += __shfl_xor_sync(0xffffffffu, v, 4);
        v += __shfl_xor_sync(0xffffffffu, v, 2);
        v += __shfl_xor_sync(0xffffffffu, v, 1);
        kv[i] = v;
    }
    const int lane = t & 31, wid = t >> 5;
    if (lane == 0) {
#pragma unroll
        for (int i = 0; i < 72; i++) red[wid][i] = kv[i];
    }
    __syncthreads();
    if (t < 72) {
        float s = 0.f;
#pragma unroll
        for (int w = 0; w < 8; w++) s += red[w][t];
        kvf[t] = s;
    }
    __syncthreads();

    uint32_t* dsth = g_atth + (size_t)b * HW * KWA + h * 4;
    uint32_t* dstl = g_attl + (size_t)b * HW * KWA + h * 4;
#pragma unroll
    for (int it = 0; it < HW / 512; it++) {
        int p = (it * 256 + t) * 2;
        float2 qd[8];
#pragma unroll
        for (int d = 0; d < 8; d++) {
            float2 v = *(const float2*)&base[(size_t)d * HW + p];
            qd[d].x = fmaxf(v.x, 0.f);
            qd[d].y = fmaxf(v.y, 0.f);
        }
#pragma unroll
        for (int px = 0; px < 2; px++) {
            float num[9];
#pragma unroll
            for (int e = 0; e < 9; e++) {
                float s = 0.f;
#pragma unroll
                for (int d = 0; d < 8; d++) {
                    float q = px ? qd[d].y : qd[d].x;
                    s = fmaf(q, kvf[d * 9 + e], s);
                }
                num[e] = s;
            }
            float inv = 1.f / (num[8] + EPSV);
            uint32_t hw4[4], lw4[4];
#pragma unroll
            for (int j = 0; j < 4; j++) {
                uint16_t h0, l0, h1, l1;
                split_bf16(num[2 * j] * inv, h0, l0);
                split_bf16(num[2 * j + 1] * inv, h1, l1);
                hw4[j] = pack2(h0, h1);
                lw4[j] = pack2(l0, l1);
            }
            *(uint4*)(dsth + (size_t)(p + px) * KWA) =
                make_uint4(hw4[0], hw4[1], hw4[2], hw4[3]);
            *(uint4*)(dstl + (size_t)(p + px) * KWA) =
                make_uint4(lw4[0], lw4[1], lw4[2], lw4[3]);
        }
    }
}

// ---------------------------------------------------------------------------
extern "C" void kernel_launch(void* const* d_in, const int* in_sizes, int n_in,
                              void* d_out, int out_size)
{
    const float* x       = (const float*)d_in[0];
    const float* w_qkv   = (const float*)d_in[1];
    const float* w_dw    = (const float*)d_in[2];
    const float* w_pw    = (const float*)d_in[3];
    const float* w_proj  = (const float*)d_in[4];
    const float* bn_g    = (const float*)d_in[5];
    const float* bn_b    = (const float*)d_in[6];
    const float* bn_m    = (const float*)d_in[7];
    const float* bn_v    = (const float*)d_in[8];
    float* out = (float*)d_out;

    float *qkv_p;
    uint32_t *xh_p, *xl_p, *ath_p, *atl_p, *wqh_p, *wql_p, *wph_p, *wpl_p;
    cudaGetSymbolAddress((void**)&qkv_p, g_qkv);
    cudaGetSymbolAddress((void**)&xh_p,  g_xh);
    cudaGetSymbolAddress((void**)&xl_p,  g_xl);
    cudaGetSymbolAddress((void**)&ath_p, g_atth);
    cudaGetSymbolAddress((void**)&atl_p, g_attl);
    cudaGetSymbolAddress((void**)&wqh_p, g_wqh);
    cudaGetSymbolAddress((void**)&wql_p, g_wql);
    cudaGetSymbolAddress((void**)&wph_p, g_wph);
    cudaGetSymbolAddress((void**)&wpl_p, g_wpl);

    cudaFuncSetAttribute(mma_gemm_kernel<false>,
                         cudaFuncAttributeMaxDynamicSharedMemorySize, SMEM_BYTES);
    cudaFuncSetAttribute(mma_gemm_kernel<true>,
                         cudaFuncAttributeMaxDynamicSharedMemorySize, SMEM_BYTES);

    // 0) pre-split weights (one launch) + x
    const int NW1 = QKVCH * KWX, NW2 = CIN * KWA;
    presplit_w_kernel<<<(NW1 + NW2 + 255) / 256, 256>>>(
        w_qkv, wqh_p, wql_p, NW1, w_proj, wph_p, wpl_p, NW2);
    presplit_x_kernel<<<dim3(HW / 32, CIN / 128, NB), 256>>>(x, xh_p, xl_p);

    // 1) qkv = x @ w_qkv
    mma_gemm_kernel<false><<<dim3(128, QKVCH / 128), 256, SMEM_BYTES>>>(
        xh_p, xl_p, wqh_p, wql_p, qkv_p, CIN, QKVCH,
        nullptr, nullptr, nullptr, nullptr);

    // 2) depthwise 5x5 + grouped pointwise 8x8
    dwpw_kernel<<<dim3(HH / 8, NGROUP, NB), 256>>>(w_dw, w_pw);

    // 3) linear attention (single phase, float2 loads)
    attn_kernel<<<dim3(NHEAD, NB), 256>>>();

    // 4) proj GEMM + BN affine
    mma_gemm_kernel<true><<<dim3(128, CIN / 128), 256, SMEM_BYTES>>>(
        ath_p, atl_p, wph_p, wpl_p, out, ATTNCH, CIN,
        bn_g, bn_b, bn_m, bn_v);
}